// round 15
// baseline (speedup 1.0000x reference)
#include <cuda_runtime.h>
#include <math.h>

#define HH 192
#define WW 192
#define HWXY (HH*WW)        // 36864
#define CDIM 48
#define NHEADS 2
#define HD 24
#define KK 7
#define HID 127
#define HID2 254
#define CG 64               // coset grid 64x64
#define NQKVBLK 288

typedef unsigned long long u64;

// ---------------- f32x2 packed-math helpers ----------------
__device__ __forceinline__ u64 dup2(float w) {
    u64 r;
    unsigned int wi = __float_as_uint(w);
    asm("mov.b64 %0, {%1, %1};" : "=l"(r) : "r"(wi));
    return r;
}
__device__ __forceinline__ void fma2(u64& d, u64 a, u64 b) {
    asm("fma.rn.f32x2 %0, %1, %2, %3;" : "=l"(d) : "l"(a), "l"(b), "l"(d));
}
__device__ __forceinline__ void mul2(u64& d, u64 a) {
    asm("mul.rn.f32x2 %0, %1, %2;" : "=l"(d) : "l"(d), "l"(a));
}
__device__ __forceinline__ float2 unp2(u64 v) {
    unsigned int a, b;
    asm("mov.b64 {%0, %1}, %2;" : "=r"(a), "=r"(b) : "l"(v));
    return make_float2(__uint_as_float(a), __uint_as_float(b));
}

// ---------------- scratch ----------------
__device__ float g_qc[NHEADS*9*CG*CG*HD];   // [head][coset][row*64+col][24]
__device__ float g_kc[NHEADS*9*CG*CG*HD];
__device__ float g_vc[NHEADS*9*CG*CG*HD];
__device__ float g_attn[CDIM*HWXY];         // pixel-major [p][48]
__device__ float g_xn2[CDIM*HWXY];          // channel-major
__device__ float g_t[HID2*HWXY];            // channel-major
__device__ float g_g[HID*HWXY];             // channel-major
__device__ float g_pmean_part[NQKVBLK*CDIM];

// ---------------- K1: LN1 + QKV projection fused, direct coset stores ----------------
// smem: sw[144][48] + sx[48][132]
#define QKV_SMEM ((144*48 + 48*132)*4)
__global__ void __launch_bounds__(288) qkv_kernel(const float* __restrict__ x,
                                                  const float* __restrict__ lnw,
                                                  const float* __restrict__ lnb,
                                                  const float* __restrict__ qw,
                                                  const float* __restrict__ qb) {
    extern __shared__ float sm[];
    float* sw = sm;             // [144][48]
    float* sx = sm + 144*48;    // [48][132]
    int tid = threadIdx.x;
    int p0 = blockIdx.x * 128;

    for (int i = tid; i < 144*48; i += 288) sw[i] = qw[i];
    if (tid < 128) {
        int p = p0 + tid;
        float v[CDIM];
        float s = 0.f;
#pragma unroll
        for (int c = 0; c < CDIM; c++) { v[c] = x[c*HWXY + p]; s += v[c]; }
        float mu = s * (1.f/CDIM);
        float var = 0.f;
#pragma unroll
        for (int c = 0; c < CDIM; c++) { float d = v[c]-mu; var += d*d; }
        float inv = rsqrtf(var*(1.f/CDIM) + 1e-5f);
#pragma unroll
        for (int c = 0; c < CDIM; c++)
            sx[c*132 + tid] = (v[c]-mu)*inv*lnw[c] + lnb[c];
    }
    __syncthreads();

    if (tid < 48) {
        float s = 0.f;
        for (int px = 0; px < 128; px++) s += sx[tid*132 + px];
        g_pmean_part[blockIdx.x*48 + tid] = s;
    }

    int og = tid / 16, pg = tid & 15;   // og 0..17, pg 0..15
    int o0 = og * 8, px0 = pg * 8;
    u64 acc2[8][4];
#pragma unroll
    for (int a = 0; a < 8; a++)
#pragma unroll
        for (int bi = 0; bi < 4; bi++) acc2[a][bi] = 0ULL;

    for (int c4 = 0; c4 < 48; c4 += 4) {
        u64 xs2[4][4];
#pragma unroll
        for (int r = 0; r < 4; r++) {
            ulonglong2 a = *(const ulonglong2*)&sx[(c4+r)*132 + px0];
            ulonglong2 b = *(const ulonglong2*)&sx[(c4+r)*132 + px0 + 4];
            xs2[r][0]=a.x; xs2[r][1]=a.y; xs2[r][2]=b.x; xs2[r][3]=b.y;
        }
#pragma unroll
        for (int oo = 0; oo < 8; oo++) {
            float4 w4 = *(const float4*)&sw[(o0+oo)*48 + c4];
            u64 w2[4] = {dup2(w4.x), dup2(w4.y), dup2(w4.z), dup2(w4.w)};
#pragma unroll
            for (int r = 0; r < 4; r++)
#pragma unroll
                for (int p2 = 0; p2 < 4; p2++)
                    fma2(acc2[oo][p2], w2[r], xs2[r][p2]);
        }
    }

    // epilogue: bias (+q scale), direct coset stores (8 channels contiguous)
    const float qs = rsqrtf(24.0f);
    int tsel = o0 / 48;             // 0=q,1=k,2=v
    int cbase = o0 % 48;
    int n = cbase / 24, hc0 = cbase % 24;
    float* dst = (tsel == 0) ? g_qc : (tsel == 1) ? g_kc : g_vc;
    float scale = (tsel == 0) ? qs : 1.f;
    float bia[8];
#pragma unroll
    for (int oo = 0; oo < 8; oo++) bia[oo] = qb[o0+oo];

    float vals[8][8];
#pragma unroll
    for (int oo = 0; oo < 8; oo++)
#pragma unroll
        for (int p2 = 0; p2 < 4; p2++) {
            float2 v = unp2(acc2[oo][p2]);
            vals[oo][2*p2]   = (v.x + bia[oo]) * scale;
            vals[oo][2*p2+1] = (v.y + bia[oo]) * scale;
        }
#pragma unroll
    for (int px = 0; px < 8; px++) {
        int p = p0 + px0 + px;
        int i = p / WW, j = p % WW;
        int cs = (i%3)*3 + (j%3);
        int cpix = (i/3)*CG + (j/3);
        size_t base = ((size_t)(n*9 + cs)*CG*CG + cpix)*HD + hc0;
        *(float4*)&dst[base]     = make_float4(vals[0][px], vals[1][px], vals[2][px], vals[3][px]);
        *(float4*)&dst[base + 4] = make_float4(vals[4][px], vals[5][px], vals[6][px], vals[7][px]);
    }
}

// ---------------- K2: coset-tiled neighborhood attention (f32x2) ----------------
#define CHS 28
#define ATTN_SMEM ((484*CHS*2 + 176)*4)
__global__ void __launch_bounds__(256, 2) attn_kernel(const float* __restrict__ rpb) {
    extern __shared__ float sm[];
    float* sk = sm;                 // [484][28]
    float* sv = sm + 484*CHS;       // [484][28]
    float* srpb = sm + 2*484*CHS;   // [169]
    int tid = threadIdx.x;
    int tr = blockIdx.x >> 2, tc = blockIdx.x & 3;
    int cs = blockIdx.y;
    int n  = blockIdx.z;
    int r0 = tr * 16, c0 = tc * 16;
    int rbase = r0 - 3, cbase = c0 - 3;
    size_t tbase = (size_t)(n*9 + cs)*CG*CG;

    for (int i = tid; i < 169; i += 256) srpb[i] = rpb[n*169 + i];
    for (int idx = tid; idx < 2*2904; idx += 256) {
        int tsel = idx >= 2904;
        int e = tsel ? idx - 2904 : idx;
        int pos = e / 6, c4 = e % 6;
        int lr = pos / 22, lc = pos % 22;
        int grow = rbase + lr, gcol = cbase + lc;
        if (grow >= 0 && grow < CG && gcol >= 0 && gcol < CG) {
            const float* gsrc = tsel ? g_vc : g_kc;
            float* dst = tsel ? sv : sk;
            float4 val = *(const float4*)&gsrc[(tbase + grow*CG + gcol)*HD + c4*4];
            *(float4*)&dst[pos*CHS + c4*4] = val;
        }
    }
    __syncthreads();

    int tx = tid & 15, ty = tid >> 4;
    int ii = r0 + ty, jj = c0 + tx;
    int ssr = ii - 3; if (ssr < 0) ssr = 0; if (ssr > CG-KK) ssr = CG-KK;
    int ssc = jj - 3; if (ssc < 0) ssc = 0; if (ssc > CG-KK) ssc = CG-KK;
    int lr0 = ssr - rbase, lc0 = ssc - cbase;
    int pbh0 = ssr - ii + 6, pbw0 = ssc - jj + 6;

    u64 q2[12];
    {
        const ulonglong2* qp = (const ulonglong2*)&g_qc[(tbase + (size_t)ii*CG + jj)*HD];
#pragma unroll
        for (int c = 0; c < 6; c++) { ulonglong2 t2 = qp[c]; q2[2*c]=t2.x; q2[2*c+1]=t2.y; }
    }

    float m = -1e30f, s = 0.f;
    u64 acc2[12];
#pragma unroll
    for (int c = 0; c < 12; c++) acc2[c] = 0ULL;

    for (int x = 0; x < KK; x++) {
        int rowb = (lr0 + x) * 22 + lc0;
        const float* brow = srpb + (pbh0 + x)*13 + pbw0;
#pragma unroll
        for (int y = 0; y < KK; y++) {
            const ulonglong2* kp = (const ulonglong2*)(sk + (rowb + y) * CHS);
            u64 d2 = 0ULL;
#pragma unroll
            for (int c = 0; c < 6; c++) {
                ulonglong2 kk = kp[c];
                fma2(d2, q2[2*c],   kk.x);
                fma2(d2, q2[2*c+1], kk.y);
            }
            float2 dd = unp2(d2);
            float d = dd.x + dd.y + brow[y];
            if (d > m) {
                float f = __expf(m - d);
                s *= f;
                u64 f2 = dup2(f);
#pragma unroll
                for (int c = 0; c < 12; c++) mul2(acc2[c], f2);
                m = d;
            }
            float w = __expf(d - m);
            s += w;
            u64 w2 = dup2(w);
            const ulonglong2* vp = (const ulonglong2*)(sv + (rowb + y) * CHS);
#pragma unroll
            for (int c = 0; c < 6; c++) {
                ulonglong2 vv = vp[c];
                fma2(acc2[2*c],   w2, vv.x);
                fma2(acc2[2*c+1], w2, vv.y);
            }
        }
    }
    float inv = 1.f / s;
    u64 inv2 = dup2(inv);
#pragma unroll
    for (int c = 0; c < 12; c++) mul2(acc2[c], inv2);
    int a = cs / 3, b = cs % 3;
    int gp = (a + 3*ii)*WW + (b + 3*jj);
    ulonglong2* op = (ulonglong2*)&g_attn[(size_t)gp*CDIM + n*HD];
#pragma unroll
    for (int c = 0; c < 6; c++) {
        ulonglong2 t2; t2.x = acc2[2*c]; t2.y = acc2[2*c+1];
        op[c] = t2;
    }
}

// ---------------- K3: proj + ECA gate + residual + LN2 fused (R11 form) ----------------
#define PROJ_SMEM ((48*48 + 48*132 + 48*132 + 48 + 48)*4)
__global__ void __launch_bounds__(192) proj_kernel(const float* __restrict__ x,
                            const float* __restrict__ pw,
                            const float* __restrict__ pb,
                            const float* __restrict__ ew,
                            const float* __restrict__ ln2w,
                            const float* __restrict__ ln2b,
                            float* __restrict__ out) {
    extern __shared__ float sm[];
    float* sw = sm;                 // [48][48]
    float* sa = sm + 48*48;         // [48][132]
    float* so = sa + 48*132;        // [48][132]
    float* smean = so + 48*132;     // [48]
    float* sgate = smean + 48;      // [48]
    int tid = threadIdx.x;
    int p0 = blockIdx.x * 128;

    for (int i = tid; i < 48*48; i += 192) sw[i] = pw[i];
    for (int i = tid; i < 48*128; i += 192) {
        int px = i / 48, c = i % 48;
        sa[c*132 + px] = g_attn[(size_t)(p0+px)*CDIM + c];
    }
    if (tid < 48) {
        float s = 0.f;
        for (int k = 0; k < NQKVBLK; k++) s += g_pmean_part[k*48 + tid];
        smean[tid] = s * (1.f/HWXY);
    }
    __syncthreads();
    if (tid < 48) {
        float s = 0.f;
#pragma unroll
        for (int k = 0; k < 7; k++) {
            int cc = tid - 3 + k;
            if (cc >= 0 && cc < CDIM) s += ew[k] * smean[cc];
        }
        sgate[tid] = 1.f / (1.f + expf(-s));
    }

    int og = tid >> 4, pg = tid & 15;
    int o0 = og * 4, px0 = pg * 8;
    u64 acc2[4][4];
#pragma unroll
    for (int a = 0; a < 4; a++)
#pragma unroll
        for (int bi = 0; bi < 4; bi++) acc2[a][bi] = 0ULL;

    for (int c4 = 0; c4 < 48; c4 += 4) {
        u64 xs2[4][4];
#pragma unroll
        for (int r = 0; r < 4; r++) {
            ulonglong2 a = *(const ulonglong2*)&sa[(c4+r)*132 + px0];
            ulonglong2 b = *(const ulonglong2*)&sa[(c4+r)*132 + px0 + 4];
            xs2[r][0]=a.x; xs2[r][1]=a.y; xs2[r][2]=b.x; xs2[r][3]=b.y;
        }
#pragma unroll
        for (int oo = 0; oo < 4; oo++) {
            float4 w4 = *(const float4*)&sw[(o0+oo)*48 + c4];
            u64 w2[4] = {dup2(w4.x), dup2(w4.y), dup2(w4.z), dup2(w4.w)};
#pragma unroll
            for (int r = 0; r < 4; r++)
#pragma unroll
                for (int p2 = 0; p2 < 4; p2++)
                    fma2(acc2[oo][p2], w2[r], xs2[r][p2]);
        }
    }
    __syncthreads();

#pragma unroll
    for (int oo = 0; oo < 4; oo++) {
        int o = o0 + oo;
        float g = sgate[o];
        float b = pb[o];
        float vals[8];
#pragma unroll
        for (int p2 = 0; p2 < 4; p2++) {
            float2 v = unp2(acc2[oo][p2]);
            vals[2*p2] = v.x; vals[2*p2+1] = v.y;
        }
        float4 xv1 = *(const float4*)&x[(size_t)o*HWXY + p0 + px0];
        float4 xv2 = *(const float4*)&x[(size_t)o*HWXY + p0 + px0 + 4];
        vals[0] = xv1.x + g*(vals[0]+b); vals[1] = xv1.y + g*(vals[1]+b);
        vals[2] = xv1.z + g*(vals[2]+b); vals[3] = xv1.w + g*(vals[3]+b);
        vals[4] = xv2.x + g*(vals[4]+b); vals[5] = xv2.y + g*(vals[5]+b);
        vals[6] = xv2.z + g*(vals[6]+b); vals[7] = xv2.w + g*(vals[7]+b);
        *(float4*)&out[(size_t)o*HWXY + p0 + px0]     = make_float4(vals[0],vals[1],vals[2],vals[3]);
        *(float4*)&out[(size_t)o*HWXY + p0 + px0 + 4] = make_float4(vals[4],vals[5],vals[6],vals[7]);
#pragma unroll
        for (int px = 0; px < 8; px++) so[o*132 + px0 + px] = vals[px];
    }
    __syncthreads();

    if (tid < 128) {
        int px = tid;
        float v[CDIM];
        float s = 0.f;
#pragma unroll
        for (int c = 0; c < CDIM; c++) { v[c] = so[c*132 + px]; s += v[c]; }
        float mu = s * (1.f/CDIM);
        float var = 0.f;
#pragma unroll
        for (int c = 0; c < CDIM; c++) { float d = v[c]-mu; var += d*d; }
        float inv = rsqrtf(var*(1.f/CDIM) + 1e-5f);
#pragma unroll
        for (int c = 0; c < CDIM; c++)
            g_xn2[c*HWXY + p0 + px] = (v[c]-mu)*inv*ln2w[c] + ln2b[c];
    }
}

// ---------------- K4: FFN in-projection, persistent weights, 2x64px tiles, grid 576 ----------------
#define FIN_SMEM ((128*48 + 48*64)*4)
__global__ void __launch_bounds__(256, 3) ffn_in_kernel(const float* __restrict__ wi) {
    extern __shared__ float sm[];
    float* sw = sm;               // [128][48], row 127 zero
    float* sx = sm + 128*48;      // [48][64]
    int tid = threadIdx.x;
    int h  = blockIdx.y;
    int obase = h * HID;

    for (int i = tid; i < 128*48; i += 256) {
        int r = i / 48;
        sw[i] = (r < HID) ? wi[(obase + r)*48 + (i - r*48)] : 0.f;
    }

    int og = tid >> 4, pg = tid & 15;   // og 0..15, pg 0..15
    int o0 = og * 8, px0 = pg * 4;

    for (int t = 0; t < 2; t++) {
        int p0 = (blockIdx.x * 2 + t) * 64;
        __syncthreads();
        for (int i = tid; i < 48*64; i += 256) {
            int c = i >> 6, px = i & 63;
            sx[i] = g_xn2[c*HWXY + p0 + px];
        }
        __syncthreads();

        u64 acc2[8][2];
#pragma unroll
        for (int a = 0; a < 8; a++) { acc2[a][0] = 0ULL; acc2[a][1] = 0ULL; }

        for (int c4 = 0; c4 < 48; c4 += 4) {
            u64 xs2[4][2];
#pragma unroll
            for (int r = 0; r < 4; r++) {
                ulonglong2 a = *(const ulonglong2*)&sx[(c4+r)*64 + px0];
                xs2[r][0]=a.x; xs2[r][1]=a.y;
            }
#pragma unroll
            for (int oo = 0; oo < 8; oo++) {
                float4 w4 = *(const float4*)&sw[(o0+oo)*48 + c4];
                u64 w2[4] = {dup2(w4.x), dup2(w4.y), dup2(w4.z), dup2(w4.w)};
#pragma unroll
                for (int r = 0; r < 4; r++) {
                    fma2(acc2[oo][0], w2[r], xs2[r][0]);
                    fma2(acc2[oo][1], w2[r], xs2[r][1]);
                }
            }
        }
#pragma unroll
        for (int oo = 0; oo < 8; oo++) {
            int ol = o0 + oo;
            if (ol < HID) {
                float2 v0 = unp2(acc2[oo][0]);
                float2 v1 = unp2(acc2[oo][1]);
                *(float4*)&g_t[(size_t)(obase+ol)*HWXY + p0 + px0] =
                    make_float4(v0.x, v0.y, v1.x, v1.y);
            }
        }
    }
}

// ---------------- K5: depthwise 3x3 + exact-gelu, padded rows, 16-row bands ----------------
__global__ void dwgelu_kernel(const float* __restrict__ wdw) {
    __shared__ float sA[18*196];
    __shared__ float sB[18*196];
    __shared__ float swc[18];
    int o = blockIdx.y;
    int r0 = blockIdx.x * 16;
    int tid = threadIdx.x;

    if (tid < 9)  swc[tid] = wdw[o*9 + tid];
    else if (tid < 18) swc[tid] = wdw[(o+HID)*9 + tid - 9];

    for (int i = tid; i < 18*196; i += 256) {
        int rr = i / 196, col = i - rr*196;
        int row = r0 - 1 + rr;
        int gcol = col - 1;
        bool ok = (row >= 0) && (row < HH) && (gcol >= 0) && (gcol < WW);
        sA[i] = ok ? g_t[(size_t)o*HWXY + row*WW + gcol] : 0.f;
        sB[i] = ok ? g_t[(size_t)(o+HID)*HWXY + row*WW + gcol] : 0.f;
    }
    __syncthreads();

    for (int idx = tid; idx < 16*192; idx += 256) {
        int orow = idx / 192, col = idx - orow*192;
        int sbase = (orow + 1) * 196 + (col + 1);
        float a = 0.f, bb = 0.f;
#pragma unroll
        for (int ky = 0; ky < 3; ky++) {
            int rb = sbase + (ky-1)*196;
#pragma unroll
            for (int kx = 0; kx < 3; kx++) {
                a  += swc[ky*3+kx]     * sA[rb + kx - 1];
                bb += swc[9 + ky*3+kx] * sB[rb + kx - 1];
            }
        }
        float ge = 0.5f * a * (1.f + erff(a * 0.70710678118654752f));
        g_g[(size_t)o*HWXY + (r0+orow)*WW + col] = ge * bb;
    }
}

// ---------------- K6: FFN out-projection + residual, persistent weights, 1x64px, grid 576 ----------------
#define FOUT_SMEM ((48*128 + 128*64)*4)
__global__ void __launch_bounds__(192, 3) ffn_out_kernel(const float* __restrict__ wo,
                               float* __restrict__ out) {
    extern __shared__ float sm[];
    float* sw = sm;             // [48][128], col 127 zero
    float* sg = sm + 48*128;    // [128][64], row 127 zero
    int tid = threadIdx.x;
    int p0 = blockIdx.x * 64;

    for (int i = tid; i < 48*128; i += 192) {
        int o = i >> 7, c = i & 127;
        sw[i] = (c < HID) ? wo[o*HID + c] : 0.f;
    }
    for (int i = tid; i < 64; i += 192) sg[127*64 + i] = 0.f;
    for (int i = tid; i < HID*64; i += 192) {
        int c = i >> 6, px = i & 63;
        sg[i] = g_g[(size_t)c*HWXY + p0 + px];
    }
    __syncthreads();

    int og = tid >> 4, pg = tid & 15;   // og 0..11, pg 0..15
    int o0 = og * 4, px0 = pg * 4;

    u64 acc2[4][2];
#pragma unroll
    for (int a = 0; a < 4; a++) { acc2[a][0] = 0ULL; acc2[a][1] = 0ULL; }

    for (int c4 = 0; c4 < 128; c4 += 4) {
        u64 xs2[4][2];
#pragma unroll
        for (int r = 0; r < 4; r++) {
            ulonglong2 a = *(const ulonglong2*)&sg[(c4+r)*64 + px0];
            xs2[r][0]=a.x; xs2[r][1]=a.y;
        }
#pragma unroll
        for (int oo = 0; oo < 4; oo++) {
            float4 w4 = *(const float4*)&sw[(o0+oo)*128 + c4];
            u64 w2[4] = {dup2(w4.x), dup2(w4.y), dup2(w4.z), dup2(w4.w)};
#pragma unroll
            for (int r = 0; r < 4; r++) {
                fma2(acc2[oo][0], w2[r], xs2[r][0]);
                fma2(acc2[oo][1], w2[r], xs2[r][1]);
            }
        }
    }
#pragma unroll
    for (int oo = 0; oo < 4; oo++) {
        int o = o0 + oo;
        float2 v0 = unp2(acc2[oo][0]);
        float2 v1 = unp2(acc2[oo][1]);
        float4* op = (float4*)&out[(size_t)o*HWXY + p0 + px0];
        float4 c1 = *op;
        c1.x += v0.x; c1.y += v0.y; c1.z += v1.x; c1.w += v1.y;
        *op = c1;
    }
}

// ---------------- launch ----------------
extern "C" void kernel_launch(void* const* d_in, const int* in_sizes, int n_in,
                              void* d_out, int out_size) {
    const float* x      = (const float*)d_in[0];
    const float* ln1_w  = (const float*)d_in[1];
    const float* ln1_b  = (const float*)d_in[2];
    const float* qkv_w  = (const float*)d_in[3];
    const float* qkv_b  = (const float*)d_in[4];
    const float* rpb    = (const float*)d_in[5];
    const float* proj_w = (const float*)d_in[6];
    const float* proj_b = (const float*)d_in[7];
    const float* eca_w  = (const float*)d_in[8];
    const float* ln2_w  = (const float*)d_in[9];
    const float* ln2_b  = (const float*)d_in[10];
    const float* w_in   = (const float*)d_in[11];
    const float* w_dw   = (const float*)d_in[12];
    const float* w_out  = (const float*)d_in[13];
    float* out = (float*)d_out;

    cudaFuncSetAttribute(qkv_kernel,     cudaFuncAttributeMaxDynamicSharedMemorySize, QKV_SMEM);
    cudaFuncSetAttribute(attn_kernel,    cudaFuncAttributeMaxDynamicSharedMemorySize, ATTN_SMEM);
    cudaFuncSetAttribute(proj_kernel,    cudaFuncAttributeMaxDynamicSharedMemorySize, PROJ_SMEM);
    cudaFuncSetAttribute(ffn_in_kernel,  cudaFuncAttributeMaxDynamicSharedMemorySize, FIN_SMEM);
    cudaFuncSetAttribute(ffn_out_kernel, cudaFuncAttributeMaxDynamicSharedMemorySize, FOUT_SMEM);

    qkv_kernel<<<NQKVBLK, 288, QKV_SMEM>>>(x, ln1_w, ln1_b, qkv_w, qkv_b);
    attn_kernel<<<dim3(16, 9, 2), 256, ATTN_SMEM>>>(rpb);
    proj_kernel<<<HWXY/128, 192, PROJ_SMEM>>>(x, proj_w, proj_b, eca_w, ln2_w, ln2_b, out);
    ffn_in_kernel<<<dim3(288, 2), 256, FIN_SMEM>>>(w_in);
    dwgelu_kernel<<<dim3(HH/16, HID), 256>>>(w_dw);
    ffn_out_kernel<<<HWXY/64, 192, FOUT_SMEM>>>(w_out, out);
}

// round 16
// speedup vs baseline: 1.0129x; 1.0129x over previous
#include <cuda_runtime.h>
#include <math.h>

#define HH 192
#define WW 192
#define HWXY (HH*WW)        // 36864
#define CDIM 48
#define NHEADS 2
#define HD 24
#define KK 7
#define HID 127
#define HID2 254
#define CG 64               // coset grid 64x64
#define NQKVBLK 288

typedef unsigned long long u64;

// ---------------- f32x2 packed-math helpers ----------------
__device__ __forceinline__ u64 dup2(float w) {
    u64 r;
    unsigned int wi = __float_as_uint(w);
    asm("mov.b64 %0, {%1, %1};" : "=l"(r) : "r"(wi));
    return r;
}
__device__ __forceinline__ void fma2(u64& d, u64 a, u64 b) {
    asm("fma.rn.f32x2 %0, %1, %2, %3;" : "=l"(d) : "l"(a), "l"(b), "l"(d));
}
__device__ __forceinline__ void mul2(u64& d, u64 a) {
    asm("mul.rn.f32x2 %0, %1, %2;" : "=l"(d) : "l"(d), "l"(a));
}
__device__ __forceinline__ float2 unp2(u64 v) {
    unsigned int a, b;
    asm("mov.b64 {%0, %1}, %2;" : "=r"(a), "=r"(b) : "l"(v));
    return make_float2(__uint_as_float(a), __uint_as_float(b));
}

// ---------------- scratch ----------------
__device__ float g_qc[NHEADS*9*CG*CG*HD];   // [head][coset][row*64+col][24]
__device__ float g_kc[NHEADS*9*CG*CG*HD];
__device__ float g_vc[NHEADS*9*CG*CG*HD];
__device__ float g_attn[CDIM*HWXY];         // pixel-major [p][48]
__device__ float g_xn2[CDIM*HWXY];          // channel-major
__device__ float g_t[HID2*HWXY];            // channel-major
__device__ float g_g[HID*HWXY];             // channel-major
__device__ float g_pmean_part[NQKVBLK*CDIM];

// ---------------- K1: LN1 + QKV projection fused, direct coset stores ----------------
// smem: sw[144][48] + sx[48][132]
#define QKV_SMEM ((144*48 + 48*132)*4)
__global__ void __launch_bounds__(288) qkv_kernel(const float* __restrict__ x,
                                                  const float* __restrict__ lnw,
                                                  const float* __restrict__ lnb,
                                                  const float* __restrict__ qw,
                                                  const float* __restrict__ qb) {
    extern __shared__ float sm[];
    float* sw = sm;             // [144][48]
    float* sx = sm + 144*48;    // [48][132]
    int tid = threadIdx.x;
    int p0 = blockIdx.x * 128;

    for (int i = tid; i < 144*48; i += 288) sw[i] = qw[i];
    if (tid < 128) {
        int p = p0 + tid;
        float v[CDIM];
        float s = 0.f;
#pragma unroll
        for (int c = 0; c < CDIM; c++) { v[c] = x[c*HWXY + p]; s += v[c]; }
        float mu = s * (1.f/CDIM);
        float var = 0.f;
#pragma unroll
        for (int c = 0; c < CDIM; c++) { float d = v[c]-mu; var += d*d; }
        float inv = rsqrtf(var*(1.f/CDIM) + 1e-5f);
#pragma unroll
        for (int c = 0; c < CDIM; c++)
            sx[c*132 + tid] = (v[c]-mu)*inv*lnw[c] + lnb[c];
    }
    __syncthreads();

    if (tid < 48) {
        float s = 0.f;
        for (int px = 0; px < 128; px++) s += sx[tid*132 + px];
        g_pmean_part[blockIdx.x*48 + tid] = s;
    }

    int og = tid / 16, pg = tid & 15;   // og 0..17, pg 0..15
    int o0 = og * 8, px0 = pg * 8;
    u64 acc2[8][4];
#pragma unroll
    for (int a = 0; a < 8; a++)
#pragma unroll
        for (int bi = 0; bi < 4; bi++) acc2[a][bi] = 0ULL;

    for (int c4 = 0; c4 < 48; c4 += 4) {
        u64 xs2[4][4];
#pragma unroll
        for (int r = 0; r < 4; r++) {
            ulonglong2 a = *(const ulonglong2*)&sx[(c4+r)*132 + px0];
            ulonglong2 b = *(const ulonglong2*)&sx[(c4+r)*132 + px0 + 4];
            xs2[r][0]=a.x; xs2[r][1]=a.y; xs2[r][2]=b.x; xs2[r][3]=b.y;
        }
#pragma unroll
        for (int oo = 0; oo < 8; oo++) {
            float4 w4 = *(const float4*)&sw[(o0+oo)*48 + c4];
            u64 w2[4] = {dup2(w4.x), dup2(w4.y), dup2(w4.z), dup2(w4.w)};
#pragma unroll
            for (int r = 0; r < 4; r++)
#pragma unroll
                for (int p2 = 0; p2 < 4; p2++)
                    fma2(acc2[oo][p2], w2[r], xs2[r][p2]);
        }
    }

    // epilogue: bias (+q scale), direct coset stores (8 channels contiguous)
    const float qs = rsqrtf(24.0f);
    int tsel = o0 / 48;             // 0=q,1=k,2=v
    int cbase = o0 % 48;
    int n = cbase / 24, hc0 = cbase % 24;
    float* dst = (tsel == 0) ? g_qc : (tsel == 1) ? g_kc : g_vc;
    float scale = (tsel == 0) ? qs : 1.f;
    float bia[8];
#pragma unroll
    for (int oo = 0; oo < 8; oo++) bia[oo] = qb[o0+oo];

    float vals[8][8];
#pragma unroll
    for (int oo = 0; oo < 8; oo++)
#pragma unroll
        for (int p2 = 0; p2 < 4; p2++) {
            float2 v = unp2(acc2[oo][p2]);
            vals[oo][2*p2]   = (v.x + bia[oo]) * scale;
            vals[oo][2*p2+1] = (v.y + bia[oo]) * scale;
        }
#pragma unroll
    for (int px = 0; px < 8; px++) {
        int p = p0 + px0 + px;
        int i = p / WW, j = p % WW;
        int cs = (i%3)*3 + (j%3);
        int cpix = (i/3)*CG + (j/3);
        size_t base = ((size_t)(n*9 + cs)*CG*CG + cpix)*HD + hc0;
        *(float4*)&dst[base]     = make_float4(vals[0][px], vals[1][px], vals[2][px], vals[3][px]);
        *(float4*)&dst[base + 4] = make_float4(vals[4][px], vals[5][px], vals[6][px], vals[7][px]);
    }
}

// ---------------- K2: coset-tiled neighborhood attention (f32x2) ----------------
#define CHS 28
#define ATTN_SMEM ((484*CHS*2 + 176)*4)
__global__ void __launch_bounds__(256, 2) attn_kernel(const float* __restrict__ rpb) {
    extern __shared__ float sm[];
    float* sk = sm;                 // [484][28]
    float* sv = sm + 484*CHS;       // [484][28]
    float* srpb = sm + 2*484*CHS;   // [169]
    int tid = threadIdx.x;
    int tr = blockIdx.x >> 2, tc = blockIdx.x & 3;
    int cs = blockIdx.y;
    int n  = blockIdx.z;
    int r0 = tr * 16, c0 = tc * 16;
    int rbase = r0 - 3, cbase = c0 - 3;
    size_t tbase = (size_t)(n*9 + cs)*CG*CG;

    for (int i = tid; i < 169; i += 256) srpb[i] = rpb[n*169 + i];
    for (int idx = tid; idx < 2*2904; idx += 256) {
        int tsel = idx >= 2904;
        int e = tsel ? idx - 2904 : idx;
        int pos = e / 6, c4 = e % 6;
        int lr = pos / 22, lc = pos % 22;
        int grow = rbase + lr, gcol = cbase + lc;
        if (grow >= 0 && grow < CG && gcol >= 0 && gcol < CG) {
            const float* gsrc = tsel ? g_vc : g_kc;
            float* dst = tsel ? sv : sk;
            float4 val = *(const float4*)&gsrc[(tbase + grow*CG + gcol)*HD + c4*4];
            *(float4*)&dst[pos*CHS + c4*4] = val;
        }
    }
    __syncthreads();

    int tx = tid & 15, ty = tid >> 4;
    int ii = r0 + ty, jj = c0 + tx;
    int ssr = ii - 3; if (ssr < 0) ssr = 0; if (ssr > CG-KK) ssr = CG-KK;
    int ssc = jj - 3; if (ssc < 0) ssc = 0; if (ssc > CG-KK) ssc = CG-KK;
    int lr0 = ssr - rbase, lc0 = ssc - cbase;
    int pbh0 = ssr - ii + 6, pbw0 = ssc - jj + 6;

    u64 q2[12];
    {
        const ulonglong2* qp = (const ulonglong2*)&g_qc[(tbase + (size_t)ii*CG + jj)*HD];
#pragma unroll
        for (int c = 0; c < 6; c++) { ulonglong2 t2 = qp[c]; q2[2*c]=t2.x; q2[2*c+1]=t2.y; }
    }

    float m = -1e30f, s = 0.f;
    u64 acc2[12];
#pragma unroll
    for (int c = 0; c < 12; c++) acc2[c] = 0ULL;

    for (int x = 0; x < KK; x++) {
        int rowb = (lr0 + x) * 22 + lc0;
        const float* brow = srpb + (pbh0 + x)*13 + pbw0;
#pragma unroll
        for (int y = 0; y < KK; y++) {
            const ulonglong2* kp = (const ulonglong2*)(sk + (rowb + y) * CHS);
            u64 d2 = 0ULL;
#pragma unroll
            for (int c = 0; c < 6; c++) {
                ulonglong2 kk = kp[c];
                fma2(d2, q2[2*c],   kk.x);
                fma2(d2, q2[2*c+1], kk.y);
            }
            float2 dd = unp2(d2);
            float d = dd.x + dd.y + brow[y];
            if (d > m) {
                float f = __expf(m - d);
                s *= f;
                u64 f2 = dup2(f);
#pragma unroll
                for (int c = 0; c < 12; c++) mul2(acc2[c], f2);
                m = d;
            }
            float w = __expf(d - m);
            s += w;
            u64 w2 = dup2(w);
            const ulonglong2* vp = (const ulonglong2*)(sv + (rowb + y) * CHS);
#pragma unroll
            for (int c = 0; c < 6; c++) {
                ulonglong2 vv = vp[c];
                fma2(acc2[2*c],   w2, vv.x);
                fma2(acc2[2*c+1], w2, vv.y);
            }
        }
    }
    float inv = 1.f / s;
    u64 inv2 = dup2(inv);
#pragma unroll
    for (int c = 0; c < 12; c++) mul2(acc2[c], inv2);
    int a = cs / 3, b = cs % 3;
    int gp = (a + 3*ii)*WW + (b + 3*jj);
    ulonglong2* op = (ulonglong2*)&g_attn[(size_t)gp*CDIM + n*HD];
#pragma unroll
    for (int c = 0; c < 6; c++) {
        ulonglong2 t2; t2.x = acc2[2*c]; t2.y = acc2[2*c+1];
        op[c] = t2;
    }
}

// ---------------- K3: proj + ECA gate + residual + LN2 fused (R11 form) ----------------
#define PROJ_SMEM ((48*48 + 48*132 + 48*132 + 48 + 48)*4)
__global__ void __launch_bounds__(192) proj_kernel(const float* __restrict__ x,
                            const float* __restrict__ pw,
                            const float* __restrict__ pb,
                            const float* __restrict__ ew,
                            const float* __restrict__ ln2w,
                            const float* __restrict__ ln2b,
                            float* __restrict__ out) {
    extern __shared__ float sm[];
    float* sw = sm;                 // [48][48]
    float* sa = sm + 48*48;         // [48][132]
    float* so = sa + 48*132;        // [48][132]
    float* smean = so + 48*132;     // [48]
    float* sgate = smean + 48;      // [48]
    int tid = threadIdx.x;
    int p0 = blockIdx.x * 128;

    for (int i = tid; i < 48*48; i += 192) sw[i] = pw[i];
    for (int i = tid; i < 48*128; i += 192) {
        int px = i / 48, c = i % 48;
        sa[c*132 + px] = g_attn[(size_t)(p0+px)*CDIM + c];
    }
    if (tid < 48) {
        float s = 0.f;
        for (int k = 0; k < NQKVBLK; k++) s += g_pmean_part[k*48 + tid];
        smean[tid] = s * (1.f/HWXY);
    }
    __syncthreads();
    if (tid < 48) {
        float s = 0.f;
#pragma unroll
        for (int k = 0; k < 7; k++) {
            int cc = tid - 3 + k;
            if (cc >= 0 && cc < CDIM) s += ew[k] * smean[cc];
        }
        sgate[tid] = 1.f / (1.f + expf(-s));
    }

    int og = tid >> 4, pg = tid & 15;
    int o0 = og * 4, px0 = pg * 8;
    u64 acc2[4][4];
#pragma unroll
    for (int a = 0; a < 4; a++)
#pragma unroll
        for (int bi = 0; bi < 4; bi++) acc2[a][bi] = 0ULL;

    for (int c4 = 0; c4 < 48; c4 += 4) {
        u64 xs2[4][4];
#pragma unroll
        for (int r = 0; r < 4; r++) {
            ulonglong2 a = *(const ulonglong2*)&sa[(c4+r)*132 + px0];
            ulonglong2 b = *(const ulonglong2*)&sa[(c4+r)*132 + px0 + 4];
            xs2[r][0]=a.x; xs2[r][1]=a.y; xs2[r][2]=b.x; xs2[r][3]=b.y;
        }
#pragma unroll
        for (int oo = 0; oo < 4; oo++) {
            float4 w4 = *(const float4*)&sw[(o0+oo)*48 + c4];
            u64 w2[4] = {dup2(w4.x), dup2(w4.y), dup2(w4.z), dup2(w4.w)};
#pragma unroll
            for (int r = 0; r < 4; r++)
#pragma unroll
                for (int p2 = 0; p2 < 4; p2++)
                    fma2(acc2[oo][p2], w2[r], xs2[r][p2]);
        }
    }
    __syncthreads();

#pragma unroll
    for (int oo = 0; oo < 4; oo++) {
        int o = o0 + oo;
        float g = sgate[o];
        float b = pb[o];
        float vals[8];
#pragma unroll
        for (int p2 = 0; p2 < 4; p2++) {
            float2 v = unp2(acc2[oo][p2]);
            vals[2*p2] = v.x; vals[2*p2+1] = v.y;
        }
        float4 xv1 = *(const float4*)&x[(size_t)o*HWXY + p0 + px0];
        float4 xv2 = *(const float4*)&x[(size_t)o*HWXY + p0 + px0 + 4];
        vals[0] = xv1.x + g*(vals[0]+b); vals[1] = xv1.y + g*(vals[1]+b);
        vals[2] = xv1.z + g*(vals[2]+b); vals[3] = xv1.w + g*(vals[3]+b);
        vals[4] = xv2.x + g*(vals[4]+b); vals[5] = xv2.y + g*(vals[5]+b);
        vals[6] = xv2.z + g*(vals[6]+b); vals[7] = xv2.w + g*(vals[7]+b);
        *(float4*)&out[(size_t)o*HWXY + p0 + px0]     = make_float4(vals[0],vals[1],vals[2],vals[3]);
        *(float4*)&out[(size_t)o*HWXY + p0 + px0 + 4] = make_float4(vals[4],vals[5],vals[6],vals[7]);
#pragma unroll
        for (int px = 0; px < 8; px++) so[o*132 + px0 + px] = vals[px];
    }
    __syncthreads();

    if (tid < 128) {
        int px = tid;
        float v[CDIM];
        float s = 0.f;
#pragma unroll
        for (int c = 0; c < CDIM; c++) { v[c] = so[c*132 + px]; s += v[c]; }
        float mu = s * (1.f/CDIM);
        float var = 0.f;
#pragma unroll
        for (int c = 0; c < CDIM; c++) { float d = v[c]-mu; var += d*d; }
        float inv = rsqrtf(var*(1.f/CDIM) + 1e-5f);
#pragma unroll
        for (int c = 0; c < CDIM; c++)
            g_xn2[c*HWXY + p0 + px] = (v[c]-mu)*inv*ln2w[c] + ln2b[c];
    }
}

// ---------------- K4: FFN in-projection, persistent weights, 2x64px tiles, grid 576 ----------------
#define FIN_SMEM ((128*48 + 48*64)*4)
__global__ void __launch_bounds__(256, 3) ffn_in_kernel(const float* __restrict__ wi) {
    extern __shared__ float sm[];
    float* sw = sm;               // [128][48], row 127 zero
    float* sx = sm + 128*48;      // [48][64]
    int tid = threadIdx.x;
    int h  = blockIdx.y;
    int obase = h * HID;

    for (int i = tid; i < 128*48; i += 256) {
        int r = i / 48;
        sw[i] = (r < HID) ? wi[(obase + r)*48 + (i - r*48)] : 0.f;
    }

    int og = tid >> 4, pg = tid & 15;   // og 0..15, pg 0..15
    int o0 = og * 8, px0 = pg * 4;

    for (int t = 0; t < 2; t++) {
        int p0 = (blockIdx.x * 2 + t) * 64;
        __syncthreads();
        for (int i = tid; i < 48*64; i += 256) {
            int c = i >> 6, px = i & 63;
            sx[i] = g_xn2[c*HWXY + p0 + px];
        }
        __syncthreads();

        u64 acc2[8][2];
#pragma unroll
        for (int a = 0; a < 8; a++) { acc2[a][0] = 0ULL; acc2[a][1] = 0ULL; }

        for (int c4 = 0; c4 < 48; c4 += 4) {
            u64 xs2[4][2];
#pragma unroll
            for (int r = 0; r < 4; r++) {
                ulonglong2 a = *(const ulonglong2*)&sx[(c4+r)*64 + px0];
                xs2[r][0]=a.x; xs2[r][1]=a.y;
            }
#pragma unroll
            for (int oo = 0; oo < 8; oo++) {
                float4 w4 = *(const float4*)&sw[(o0+oo)*48 + c4];
                u64 w2[4] = {dup2(w4.x), dup2(w4.y), dup2(w4.z), dup2(w4.w)};
#pragma unroll
                for (int r = 0; r < 4; r++) {
                    fma2(acc2[oo][0], w2[r], xs2[r][0]);
                    fma2(acc2[oo][1], w2[r], xs2[r][1]);
                }
            }
        }
#pragma unroll
        for (int oo = 0; oo < 8; oo++) {
            int ol = o0 + oo;
            if (ol < HID) {
                float2 v0 = unp2(acc2[oo][0]);
                float2 v1 = unp2(acc2[oo][1]);
                *(float4*)&g_t[(size_t)(obase+ol)*HWXY + p0 + px0] =
                    make_float4(v0.x, v0.y, v1.x, v1.y);
            }
        }
    }
}

// ---------------- K5: depthwise 3x3 + exact-gelu, padded rows, 8-row bands ----------------
__global__ void dwgelu_kernel(const float* __restrict__ wdw) {
    __shared__ float sA[10*196];
    __shared__ float sB[10*196];
    __shared__ float swc[18];
    int o = blockIdx.y;
    int r0 = blockIdx.x * 8;
    int tid = threadIdx.x;

    if (tid < 9)  swc[tid] = wdw[o*9 + tid];
    else if (tid < 18) swc[tid] = wdw[(o+HID)*9 + tid - 9];

    for (int i = tid; i < 10*196; i += 256) {
        int rr = i / 196, col = i - rr*196;
        int row = r0 - 1 + rr;
        int gcol = col - 1;
        bool ok = (row >= 0) && (row < HH) && (gcol >= 0) && (gcol < WW);
        sA[i] = ok ? g_t[(size_t)o*HWXY + row*WW + gcol] : 0.f;
        sB[i] = ok ? g_t[(size_t)(o+HID)*HWXY + row*WW + gcol] : 0.f;
    }
    __syncthreads();

    for (int idx = tid; idx < 8*192; idx += 256) {
        int orow = idx / 192, col = idx - orow*192;
        int sbase = (orow + 1) * 196 + (col + 1);
        float a = 0.f, bb = 0.f;
#pragma unroll
        for (int ky = 0; ky < 3; ky++) {
            int rb = sbase + (ky-1)*196;
#pragma unroll
            for (int kx = 0; kx < 3; kx++) {
                a  += swc[ky*3+kx]     * sA[rb + kx - 1];
                bb += swc[9 + ky*3+kx] * sB[rb + kx - 1];
            }
        }
        float ge = 0.5f * a * (1.f + erff(a * 0.70710678118654752f));
        g_g[(size_t)o*HWXY + (r0+orow)*WW + col] = ge * bb;
    }
}

// ---------------- K6: FFN out-projection + residual, persistent weights, 2x64px tiles ----------------
#define FOUT_SMEM ((48*128 + 128*64)*4)
__global__ void __launch_bounds__(192, 3) ffn_out_kernel(const float* __restrict__ wo,
                               float* __restrict__ out) {
    extern __shared__ float sm[];
    float* sw = sm;             // [48][128], col 127 zero
    float* sg = sm + 48*128;    // [128][64], row 127 zero
    int tid = threadIdx.x;

    for (int i = tid; i < 48*128; i += 192) {
        int o = i >> 7, c = i & 127;
        sw[i] = (c < HID) ? wo[o*HID + c] : 0.f;
    }
    for (int i = tid; i < 64; i += 192) sg[127*64 + i] = 0.f;

    int og = tid >> 4, pg = tid & 15;   // og 0..11, pg 0..15
    int o0 = og * 4, px0 = pg * 4;

    for (int t = 0; t < 2; t++) {
        int p0 = (blockIdx.x * 2 + t) * 64;
        __syncthreads();
        for (int i = tid; i < HID*64; i += 192) {
            int c = i >> 6, px = i & 63;
            sg[i] = g_g[(size_t)c*HWXY + p0 + px];
        }
        __syncthreads();

        u64 acc2[4][2];
#pragma unroll
        for (int a = 0; a < 4; a++) { acc2[a][0] = 0ULL; acc2[a][1] = 0ULL; }

        for (int c4 = 0; c4 < 128; c4 += 4) {
            u64 xs2[4][2];
#pragma unroll
            for (int r = 0; r < 4; r++) {
                ulonglong2 a = *(const ulonglong2*)&sg[(c4+r)*64 + px0];
                xs2[r][0]=a.x; xs2[r][1]=a.y;
            }
#pragma unroll
            for (int oo = 0; oo < 4; oo++) {
                float4 w4 = *(const float4*)&sw[(o0+oo)*128 + c4];
                u64 w2[4] = {dup2(w4.x), dup2(w4.y), dup2(w4.z), dup2(w4.w)};
#pragma unroll
                for (int r = 0; r < 4; r++) {
                    fma2(acc2[oo][0], w2[r], xs2[r][0]);
                    fma2(acc2[oo][1], w2[r], xs2[r][1]);
                }
            }
        }
#pragma unroll
        for (int oo = 0; oo < 4; oo++) {
            int o = o0 + oo;
            float2 v0 = unp2(acc2[oo][0]);
            float2 v1 = unp2(acc2[oo][1]);
            float4* op = (float4*)&out[(size_t)o*HWXY + p0 + px0];
            float4 c1 = *op;
            c1.x += v0.x; c1.y += v0.y; c1.z += v1.x; c1.w += v1.y;
            *op = c1;
        }
    }
}

// ---------------- launch ----------------
extern "C" void kernel_launch(void* const* d_in, const int* in_sizes, int n_in,
                              void* d_out, int out_size) {
    const float* x      = (const float*)d_in[0];
    const float* ln1_w  = (const float*)d_in[1];
    const float* ln1_b  = (const float*)d_in[2];
    const float* qkv_w  = (const float*)d_in[3];
    const float* qkv_b  = (const float*)d_in[4];
    const float* rpb    = (const float*)d_in[5];
    const float* proj_w = (const float*)d_in[6];
    const float* proj_b = (const float*)d_in[7];
    const float* eca_w  = (const float*)d_in[8];
    const float* ln2_w  = (const float*)d_in[9];
    const float* ln2_b  = (const float*)d_in[10];
    const float* w_in   = (const float*)d_in[11];
    const float* w_dw   = (const float*)d_in[12];
    const float* w_out  = (const float*)d_in[13];
    float* out = (float*)d_out;

    cudaFuncSetAttribute(qkv_kernel,     cudaFuncAttributeMaxDynamicSharedMemorySize, QKV_SMEM);
    cudaFuncSetAttribute(attn_kernel,    cudaFuncAttributeMaxDynamicSharedMemorySize, ATTN_SMEM);
    cudaFuncSetAttribute(proj_kernel,    cudaFuncAttributeMaxDynamicSharedMemorySize, PROJ_SMEM);
    cudaFuncSetAttribute(ffn_in_kernel,  cudaFuncAttributeMaxDynamicSharedMemorySize, FIN_SMEM);
    cudaFuncSetAttribute(ffn_out_kernel, cudaFuncAttributeMaxDynamicSharedMemorySize, FOUT_SMEM);

    qkv_kernel<<<NQKVBLK, 288, QKV_SMEM>>>(x, ln1_w, ln1_b, qkv_w, qkv_b);
    attn_kernel<<<dim3(16, 9, 2), 256, ATTN_SMEM>>>(rpb);
    proj_kernel<<<HWXY/128, 192, PROJ_SMEM>>>(x, proj_w, proj_b, eca_w, ln2_w, ln2_b, out);
    ffn_in_kernel<<<dim3(288, 2), 256, FIN_SMEM>>>(w_in);
    dwgelu_kernel<<<dim3(HH/8, HID), 256>>>(w_dw);
    ffn_out_kernel<<<288, 192, FOUT_SMEM>>>(w_out, out);
}

// round 17
// speedup vs baseline: 1.0662x; 1.0526x over previous
#include <cuda_runtime.h>
#include <math.h>

#define HH 192
#define WW 192
#define HWXY (HH*WW)        // 36864
#define CDIM 48
#define NHEADS 2
#define HD 24
#define KK 7
#define HID 127
#define HID2 254
#define CG 64               // coset grid 64x64
#define NQKVBLK 288

typedef unsigned long long u64;

// ---------------- f32x2 packed-math helpers ----------------
__device__ __forceinline__ u64 dup2(float w) {
    u64 r;
    unsigned int wi = __float_as_uint(w);
    asm("mov.b64 %0, {%1, %1};" : "=l"(r) : "r"(wi));
    return r;
}
__device__ __forceinline__ void fma2(u64& d, u64 a, u64 b) {
    asm("fma.rn.f32x2 %0, %1, %2, %3;" : "=l"(d) : "l"(a), "l"(b), "l"(d));
}
__device__ __forceinline__ void mul2(u64& d, u64 a) {
    asm("mul.rn.f32x2 %0, %1, %2;" : "=l"(d) : "l"(d), "l"(a));
}
__device__ __forceinline__ float2 unp2(u64 v) {
    unsigned int a, b;
    asm("mov.b64 {%0, %1}, %2;" : "=r"(a), "=r"(b) : "l"(v));
    return make_float2(__uint_as_float(a), __uint_as_float(b));
}

// ---------------- scratch ----------------
__device__ float g_qc[NHEADS*9*CG*CG*HD];   // [head][coset][row*64+col][24]
__device__ float g_kc[NHEADS*9*CG*CG*HD];
__device__ float g_vc[NHEADS*9*CG*CG*HD];
__device__ float g_attn[CDIM*HWXY];         // pixel-major [p][48]
__device__ float g_xn2[CDIM*HWXY];          // channel-major
__device__ float g_t[HID2*HWXY];            // channel-major
__device__ float g_g[HID*HWXY];             // channel-major
__device__ float g_pmean_part[NQKVBLK*CDIM];

// ---------------- K1: LN1 + QKV projection fused, direct coset stores ----------------
// smem: sw[144][48] + sx[48][132]
#define QKV_SMEM ((144*48 + 48*132)*4)
__global__ void __launch_bounds__(288) qkv_kernel(const float* __restrict__ x,
                                                  const float* __restrict__ lnw,
                                                  const float* __restrict__ lnb,
                                                  const float* __restrict__ qw,
                                                  const float* __restrict__ qb) {
    extern __shared__ float sm[];
    float* sw = sm;             // [144][48]
    float* sx = sm + 144*48;    // [48][132]
    int tid = threadIdx.x;
    int p0 = blockIdx.x * 128;

    for (int i = tid; i < 144*48; i += 288) sw[i] = qw[i];
    if (tid < 128) {
        int p = p0 + tid;
        float v[CDIM];
        float s = 0.f;
#pragma unroll
        for (int c = 0; c < CDIM; c++) { v[c] = x[c*HWXY + p]; s += v[c]; }
        float mu = s * (1.f/CDIM);
        float var = 0.f;
#pragma unroll
        for (int c = 0; c < CDIM; c++) { float d = v[c]-mu; var += d*d; }
        float inv = rsqrtf(var*(1.f/CDIM) + 1e-5f);
#pragma unroll
        for (int c = 0; c < CDIM; c++)
            sx[c*132 + tid] = (v[c]-mu)*inv*lnw[c] + lnb[c];
    }
    __syncthreads();

    if (tid < 48) {
        float s = 0.f;
        for (int px = 0; px < 128; px++) s += sx[tid*132 + px];
        g_pmean_part[blockIdx.x*48 + tid] = s;
    }

    int og = tid / 16, pg = tid & 15;   // og 0..17, pg 0..15
    int o0 = og * 8, px0 = pg * 8;
    u64 acc2[8][4];
#pragma unroll
    for (int a = 0; a < 8; a++)
#pragma unroll
        for (int bi = 0; bi < 4; bi++) acc2[a][bi] = 0ULL;

    for (int c4 = 0; c4 < 48; c4 += 4) {
        u64 xs2[4][4];
#pragma unroll
        for (int r = 0; r < 4; r++) {
            ulonglong2 a = *(const ulonglong2*)&sx[(c4+r)*132 + px0];
            ulonglong2 b = *(const ulonglong2*)&sx[(c4+r)*132 + px0 + 4];
            xs2[r][0]=a.x; xs2[r][1]=a.y; xs2[r][2]=b.x; xs2[r][3]=b.y;
        }
#pragma unroll
        for (int oo = 0; oo < 8; oo++) {
            float4 w4 = *(const float4*)&sw[(o0+oo)*48 + c4];
            u64 w2[4] = {dup2(w4.x), dup2(w4.y), dup2(w4.z), dup2(w4.w)};
#pragma unroll
            for (int r = 0; r < 4; r++)
#pragma unroll
                for (int p2 = 0; p2 < 4; p2++)
                    fma2(acc2[oo][p2], w2[r], xs2[r][p2]);
        }
    }

    // epilogue: bias (+q scale), direct coset stores (8 channels contiguous)
    const float qs = rsqrtf(24.0f);
    int tsel = o0 / 48;             // 0=q,1=k,2=v
    int cbase = o0 % 48;
    int n = cbase / 24, hc0 = cbase % 24;
    float* dst = (tsel == 0) ? g_qc : (tsel == 1) ? g_kc : g_vc;
    float scale = (tsel == 0) ? qs : 1.f;
    float bia[8];
#pragma unroll
    for (int oo = 0; oo < 8; oo++) bia[oo] = qb[o0+oo];

    float vals[8][8];
#pragma unroll
    for (int oo = 0; oo < 8; oo++)
#pragma unroll
        for (int p2 = 0; p2 < 4; p2++) {
            float2 v = unp2(acc2[oo][p2]);
            vals[oo][2*p2]   = (v.x + bia[oo]) * scale;
            vals[oo][2*p2+1] = (v.y + bia[oo]) * scale;
        }
#pragma unroll
    for (int px = 0; px < 8; px++) {
        int p = p0 + px0 + px;
        int i = p / WW, j = p % WW;
        int cs = (i%3)*3 + (j%3);
        int cpix = (i/3)*CG + (j/3);
        size_t base = ((size_t)(n*9 + cs)*CG*CG + cpix)*HD + hc0;
        *(float4*)&dst[base]     = make_float4(vals[0][px], vals[1][px], vals[2][px], vals[3][px]);
        *(float4*)&dst[base + 4] = make_float4(vals[4][px], vals[5][px], vals[6][px], vals[7][px]);
    }
}

// ---------------- K2: coset-tiled neighborhood attention (f32x2) ----------------
#define CHS 28
#define ATTN_SMEM ((484*CHS*2 + 176)*4)
__global__ void __launch_bounds__(256, 2) attn_kernel(const float* __restrict__ rpb) {
    extern __shared__ float sm[];
    float* sk = sm;                 // [484][28]
    float* sv = sm + 484*CHS;       // [484][28]
    float* srpb = sm + 2*484*CHS;   // [169]
    int tid = threadIdx.x;
    int tr = blockIdx.x >> 2, tc = blockIdx.x & 3;
    int cs = blockIdx.y;
    int n  = blockIdx.z;
    int r0 = tr * 16, c0 = tc * 16;
    int rbase = r0 - 3, cbase = c0 - 3;
    size_t tbase = (size_t)(n*9 + cs)*CG*CG;

    for (int i = tid; i < 169; i += 256) srpb[i] = rpb[n*169 + i];
    for (int idx = tid; idx < 2*2904; idx += 256) {
        int tsel = idx >= 2904;
        int e = tsel ? idx - 2904 : idx;
        int pos = e / 6, c4 = e % 6;
        int lr = pos / 22, lc = pos % 22;
        int grow = rbase + lr, gcol = cbase + lc;
        if (grow >= 0 && grow < CG && gcol >= 0 && gcol < CG) {
            const float* gsrc = tsel ? g_vc : g_kc;
            float* dst = tsel ? sv : sk;
            float4 val = *(const float4*)&gsrc[(tbase + grow*CG + gcol)*HD + c4*4];
            *(float4*)&dst[pos*CHS + c4*4] = val;
        }
    }
    __syncthreads();

    int tx = tid & 15, ty = tid >> 4;
    int ii = r0 + ty, jj = c0 + tx;
    int ssr = ii - 3; if (ssr < 0) ssr = 0; if (ssr > CG-KK) ssr = CG-KK;
    int ssc = jj - 3; if (ssc < 0) ssc = 0; if (ssc > CG-KK) ssc = CG-KK;
    int lr0 = ssr - rbase, lc0 = ssc - cbase;
    int pbh0 = ssr - ii + 6, pbw0 = ssc - jj + 6;

    u64 q2[12];
    {
        const ulonglong2* qp = (const ulonglong2*)&g_qc[(tbase + (size_t)ii*CG + jj)*HD];
#pragma unroll
        for (int c = 0; c < 6; c++) { ulonglong2 t2 = qp[c]; q2[2*c]=t2.x; q2[2*c+1]=t2.y; }
    }

    float m = -1e30f, s = 0.f;
    u64 acc2[12];
#pragma unroll
    for (int c = 0; c < 12; c++) acc2[c] = 0ULL;

    for (int x = 0; x < KK; x++) {
        int rowb = (lr0 + x) * 22 + lc0;
        const float* brow = srpb + (pbh0 + x)*13 + pbw0;
#pragma unroll
        for (int y = 0; y < KK; y++) {
            const ulonglong2* kp = (const ulonglong2*)(sk + (rowb + y) * CHS);
            u64 d2 = 0ULL;
#pragma unroll
            for (int c = 0; c < 6; c++) {
                ulonglong2 kk = kp[c];
                fma2(d2, q2[2*c],   kk.x);
                fma2(d2, q2[2*c+1], kk.y);
            }
            float2 dd = unp2(d2);
            float d = dd.x + dd.y + brow[y];
            if (d > m) {
                float f = __expf(m - d);
                s *= f;
                u64 f2 = dup2(f);
#pragma unroll
                for (int c = 0; c < 12; c++) mul2(acc2[c], f2);
                m = d;
            }
            float w = __expf(d - m);
            s += w;
            u64 w2 = dup2(w);
            const ulonglong2* vp = (const ulonglong2*)(sv + (rowb + y) * CHS);
#pragma unroll
            for (int c = 0; c < 6; c++) {
                ulonglong2 vv = vp[c];
                fma2(acc2[2*c],   w2, vv.x);
                fma2(acc2[2*c+1], w2, vv.y);
            }
        }
    }
    float inv = 1.f / s;
    u64 inv2 = dup2(inv);
#pragma unroll
    for (int c = 0; c < 12; c++) mul2(acc2[c], inv2);
    int a = cs / 3, b = cs % 3;
    int gp = (a + 3*ii)*WW + (b + 3*jj);
    ulonglong2* op = (ulonglong2*)&g_attn[(size_t)gp*CDIM + n*HD];
#pragma unroll
    for (int c = 0; c < 6; c++) {
        ulonglong2 t2; t2.x = acc2[2*c]; t2.y = acc2[2*c+1];
        op[c] = t2;
    }
}

// ---------------- K3: proj + ECA gate + residual + LN2 fused (R11 form) ----------------
#define PROJ_SMEM ((48*48 + 48*132 + 48*132 + 48 + 48)*4)
__global__ void __launch_bounds__(192) proj_kernel(const float* __restrict__ x,
                            const float* __restrict__ pw,
                            const float* __restrict__ pb,
                            const float* __restrict__ ew,
                            const float* __restrict__ ln2w,
                            const float* __restrict__ ln2b,
                            float* __restrict__ out) {
    extern __shared__ float sm[];
    float* sw = sm;                 // [48][48]
    float* sa = sm + 48*48;         // [48][132]
    float* so = sa + 48*132;        // [48][132]
    float* smean = so + 48*132;     // [48]
    float* sgate = smean + 48;      // [48]
    int tid = threadIdx.x;
    int p0 = blockIdx.x * 128;

    for (int i = tid; i < 48*48; i += 192) sw[i] = pw[i];
    for (int i = tid; i < 48*128; i += 192) {
        int px = i / 48, c = i % 48;
        sa[c*132 + px] = g_attn[(size_t)(p0+px)*CDIM + c];
    }
    if (tid < 48) {
        float s = 0.f;
        for (int k = 0; k < NQKVBLK; k++) s += g_pmean_part[k*48 + tid];
        smean[tid] = s * (1.f/HWXY);
    }
    __syncthreads();
    if (tid < 48) {
        float s = 0.f;
#pragma unroll
        for (int k = 0; k < 7; k++) {
            int cc = tid - 3 + k;
            if (cc >= 0 && cc < CDIM) s += ew[k] * smean[cc];
        }
        sgate[tid] = 1.f / (1.f + expf(-s));
    }

    int og = tid >> 4, pg = tid & 15;
    int o0 = og * 4, px0 = pg * 8;
    u64 acc2[4][4];
#pragma unroll
    for (int a = 0; a < 4; a++)
#pragma unroll
        for (int bi = 0; bi < 4; bi++) acc2[a][bi] = 0ULL;

    for (int c4 = 0; c4 < 48; c4 += 4) {
        u64 xs2[4][4];
#pragma unroll
        for (int r = 0; r < 4; r++) {
            ulonglong2 a = *(const ulonglong2*)&sa[(c4+r)*132 + px0];
            ulonglong2 b = *(const ulonglong2*)&sa[(c4+r)*132 + px0 + 4];
            xs2[r][0]=a.x; xs2[r][1]=a.y; xs2[r][2]=b.x; xs2[r][3]=b.y;
        }
#pragma unroll
        for (int oo = 0; oo < 4; oo++) {
            float4 w4 = *(const float4*)&sw[(o0+oo)*48 + c4];
            u64 w2[4] = {dup2(w4.x), dup2(w4.y), dup2(w4.z), dup2(w4.w)};
#pragma unroll
            for (int r = 0; r < 4; r++)
#pragma unroll
                for (int p2 = 0; p2 < 4; p2++)
                    fma2(acc2[oo][p2], w2[r], xs2[r][p2]);
        }
    }
    __syncthreads();

#pragma unroll
    for (int oo = 0; oo < 4; oo++) {
        int o = o0 + oo;
        float g = sgate[o];
        float b = pb[o];
        float vals[8];
#pragma unroll
        for (int p2 = 0; p2 < 4; p2++) {
            float2 v = unp2(acc2[oo][p2]);
            vals[2*p2] = v.x; vals[2*p2+1] = v.y;
        }
        float4 xv1 = *(const float4*)&x[(size_t)o*HWXY + p0 + px0];
        float4 xv2 = *(const float4*)&x[(size_t)o*HWXY + p0 + px0 + 4];
        vals[0] = xv1.x + g*(vals[0]+b); vals[1] = xv1.y + g*(vals[1]+b);
        vals[2] = xv1.z + g*(vals[2]+b); vals[3] = xv1.w + g*(vals[3]+b);
        vals[4] = xv2.x + g*(vals[4]+b); vals[5] = xv2.y + g*(vals[5]+b);
        vals[6] = xv2.z + g*(vals[6]+b); vals[7] = xv2.w + g*(vals[7]+b);
        *(float4*)&out[(size_t)o*HWXY + p0 + px0]     = make_float4(vals[0],vals[1],vals[2],vals[3]);
        *(float4*)&out[(size_t)o*HWXY + p0 + px0 + 4] = make_float4(vals[4],vals[5],vals[6],vals[7]);
#pragma unroll
        for (int px = 0; px < 8; px++) so[o*132 + px0 + px] = vals[px];
    }
    __syncthreads();

    if (tid < 128) {
        int px = tid;
        float v[CDIM];
        float s = 0.f;
#pragma unroll
        for (int c = 0; c < CDIM; c++) { v[c] = so[c*132 + px]; s += v[c]; }
        float mu = s * (1.f/CDIM);
        float var = 0.f;
#pragma unroll
        for (int c = 0; c < CDIM; c++) { float d = v[c]-mu; var += d*d; }
        float inv = rsqrtf(var*(1.f/CDIM) + 1e-5f);
#pragma unroll
        for (int c = 0; c < CDIM; c++)
            g_xn2[c*HWXY + p0 + px] = (v[c]-mu)*inv*ln2w[c] + ln2b[c];
    }
}

// ---------------- K4: FFN in-projection, persistent weights, 2x64px tiles staged once ----------------
// smem: sw[128][48] + sx[48][128]
#define FIN_SMEM ((128*48 + 48*128)*4)
__global__ void __launch_bounds__(256, 3) ffn_in_kernel(const float* __restrict__ wi) {
    extern __shared__ float sm[];
    float* sw = sm;               // [128][48], row 127 zero
    float* sx = sm + 128*48;      // [48][128] both tiles
    int tid = threadIdx.x;
    int h  = blockIdx.y;
    int obase = h * HID;
    int p0 = blockIdx.x * 128;

    for (int i = tid; i < 128*48; i += 256) {
        int r = i / 48;
        sw[i] = (r < HID) ? wi[(obase + r)*48 + (i - r*48)] : 0.f;
    }
    // vectorized staging of both tiles: 48*128 floats = 1536 float4
    for (int i = tid; i < 48*32; i += 256) {
        int c = i >> 5, q = i & 31;
        *(float4*)&sx[c*128 + q*4] = *(const float4*)&g_xn2[c*HWXY + p0 + q*4];
    }
    __syncthreads();

    int og = tid >> 4, pg = tid & 15;   // og 0..15, pg 0..15
    int o0 = og * 8, px0 = pg * 4;

#pragma unroll
    for (int t = 0; t < 2; t++) {
        int toff = t * 64;
        u64 acc2[8][2];
#pragma unroll
        for (int a = 0; a < 8; a++) { acc2[a][0] = 0ULL; acc2[a][1] = 0ULL; }

        for (int c4 = 0; c4 < 48; c4 += 4) {
            u64 xs2[4][2];
#pragma unroll
            for (int r = 0; r < 4; r++) {
                ulonglong2 a = *(const ulonglong2*)&sx[(c4+r)*128 + toff + px0];
                xs2[r][0]=a.x; xs2[r][1]=a.y;
            }
#pragma unroll
            for (int oo = 0; oo < 8; oo++) {
                float4 w4 = *(const float4*)&sw[(o0+oo)*48 + c4];
                u64 w2[4] = {dup2(w4.x), dup2(w4.y), dup2(w4.z), dup2(w4.w)};
#pragma unroll
                for (int r = 0; r < 4; r++) {
                    fma2(acc2[oo][0], w2[r], xs2[r][0]);
                    fma2(acc2[oo][1], w2[r], xs2[r][1]);
                }
            }
        }
#pragma unroll
        for (int oo = 0; oo < 8; oo++) {
            int ol = o0 + oo;
            if (ol < HID) {
                float2 v0 = unp2(acc2[oo][0]);
                float2 v1 = unp2(acc2[oo][1]);
                *(float4*)&g_t[(size_t)(obase+ol)*HWXY + p0 + toff + px0] =
                    make_float4(v0.x, v0.y, v1.x, v1.y);
            }
        }
    }
}

// ---------------- K5: depthwise 3x3 + exact-gelu, padded rows, 8-row bands ----------------
__global__ void dwgelu_kernel(const float* __restrict__ wdw) {
    __shared__ float sA[10*196];
    __shared__ float sB[10*196];
    __shared__ float swc[18];
    int o = blockIdx.y;
    int r0 = blockIdx.x * 8;
    int tid = threadIdx.x;

    if (tid < 9)  swc[tid] = wdw[o*9 + tid];
    else if (tid < 18) swc[tid] = wdw[(o+HID)*9 + tid - 9];

    for (int i = tid; i < 10*196; i += 256) {
        int rr = i / 196, col = i - rr*196;
        int row = r0 - 1 + rr;
        int gcol = col - 1;
        bool ok = (row >= 0) && (row < HH) && (gcol >= 0) && (gcol < WW);
        sA[i] = ok ? g_t[(size_t)o*HWXY + row*WW + gcol] : 0.f;
        sB[i] = ok ? g_t[(size_t)(o+HID)*HWXY + row*WW + gcol] : 0.f;
    }
    __syncthreads();

    for (int idx = tid; idx < 8*192; idx += 256) {
        int orow = idx / 192, col = idx - orow*192;
        int sbase = (orow + 1) * 196 + (col + 1);
        float a = 0.f, bb = 0.f;
#pragma unroll
        for (int ky = 0; ky < 3; ky++) {
            int rb = sbase + (ky-1)*196;
#pragma unroll
            for (int kx = 0; kx < 3; kx++) {
                a  += swc[ky*3+kx]     * sA[rb + kx - 1];
                bb += swc[9 + ky*3+kx] * sB[rb + kx - 1];
            }
        }
        float ge = 0.5f * a * (1.f + erff(a * 0.70710678118654752f));
        g_g[(size_t)o*HWXY + (r0+orow)*WW + col] = ge * bb;
    }
}

// ---------------- K6: FFN out-projection + residual, persistent weights, 2x64px tiles ----------------
#define FOUT_SMEM ((48*128 + 128*64)*4)
__global__ void __launch_bounds__(192, 3) ffn_out_kernel(const float* __restrict__ wo,
                               float* __restrict__ out) {
    extern __shared__ float sm[];
    float* sw = sm;             // [48][128], col 127 zero
    float* sg = sm + 48*128;    // [128][64], row 127 zero
    int tid = threadIdx.x;

    for (int i = tid; i < 48*128; i += 192) {
        int o = i >> 7, c = i & 127;
        sw[i] = (c < HID) ? wo[o*HID + c] : 0.f;
    }
    for (int i = tid; i < 64; i += 192) sg[127*64 + i] = 0.f;

    int og = tid >> 4, pg = tid & 15;   // og 0..11, pg 0..15
    int o0 = og * 4, px0 = pg * 4;

    for (int t = 0; t < 2; t++) {
        int p0 = (blockIdx.x * 2 + t) * 64;
        __syncthreads();
        // vectorized staging: HID*64 floats = HID*16 float4
        for (int i = tid; i < HID*16; i += 192) {
            int c = i >> 4, q = i & 15;
            *(float4*)&sg[c*64 + q*4] = *(const float4*)&g_g[(size_t)c*HWXY + p0 + q*4];
        }
        __syncthreads();

        u64 acc2[4][2];
#pragma unroll
        for (int a = 0; a < 4; a++) { acc2[a][0] = 0ULL; acc2[a][1] = 0ULL; }

        for (int c4 = 0; c4 < 128; c4 += 4) {
            u64 xs2[4][2];
#pragma unroll
            for (int r = 0; r < 4; r++) {
                ulonglong2 a = *(const ulonglong2*)&sg[(c4+r)*64 + px0];
                xs2[r][0]=a.x; xs2[r][1]=a.y;
            }
#pragma unroll
            for (int oo = 0; oo < 4; oo++) {
                float4 w4 = *(const float4*)&sw[(o0+oo)*128 + c4];
                u64 w2[4] = {dup2(w4.x), dup2(w4.y), dup2(w4.z), dup2(w4.w)};
#pragma unroll
                for (int r = 0; r < 4; r++) {
                    fma2(acc2[oo][0], w2[r], xs2[r][0]);
                    fma2(acc2[oo][1], w2[r], xs2[r][1]);
                }
            }
        }
#pragma unroll
        for (int oo = 0; oo < 4; oo++) {
            int o = o0 + oo;
            float2 v0 = unp2(acc2[oo][0]);
            float2 v1 = unp2(acc2[oo][1]);
            float4* op = (float4*)&out[(size_t)o*HWXY + p0 + px0];
            float4 c1 = *op;
            c1.x += v0.x; c1.y += v0.y; c1.z += v1.x; c1.w += v1.y;
            *op = c1;
        }
    }
}

// ---------------- launch ----------------
extern "C" void kernel_launch(void* const* d_in, const int* in_sizes, int n_in,
                              void* d_out, int out_size) {
    const float* x      = (const float*)d_in[0];
    const float* ln1_w  = (const float*)d_in[1];
    const float* ln1_b  = (const float*)d_in[2];
    const float* qkv_w  = (const float*)d_in[3];
    const float* qkv_b  = (const float*)d_in[4];
    const float* rpb    = (const float*)d_in[5];
    const float* proj_w = (const float*)d_in[6];
    const float* proj_b = (const float*)d_in[7];
    const float* eca_w  = (const float*)d_in[8];
    const float* ln2_w  = (const float*)d_in[9];
    const float* ln2_b  = (const float*)d_in[10];
    const float* w_in   = (const float*)d_in[11];
    const float* w_dw   = (const float*)d_in[12];
    const float* w_out  = (const float*)d_in[13];
    float* out = (float*)d_out;

    cudaFuncSetAttribute(qkv_kernel,     cudaFuncAttributeMaxDynamicSharedMemorySize, QKV_SMEM);
    cudaFuncSetAttribute(attn_kernel,    cudaFuncAttributeMaxDynamicSharedMemorySize, ATTN_SMEM);
    cudaFuncSetAttribute(proj_kernel,    cudaFuncAttributeMaxDynamicSharedMemorySize, PROJ_SMEM);
    cudaFuncSetAttribute(ffn_in_kernel,  cudaFuncAttributeMaxDynamicSharedMemorySize, FIN_SMEM);
    cudaFuncSetAttribute(ffn_out_kernel, cudaFuncAttributeMaxDynamicSharedMemorySize, FOUT_SMEM);

    qkv_kernel<<<NQKVBLK, 288, QKV_SMEM>>>(x, ln1_w, ln1_b, qkv_w, qkv_b);
    attn_kernel<<<dim3(16, 9, 2), 256, ATTN_SMEM>>>(rpb);
    proj_kernel<<<HWXY/128, 192, PROJ_SMEM>>>(x, proj_w, proj_b, eca_w, ln2_w, ln2_b, out);
    ffn_in_kernel<<<dim3(288, 2), 256, FIN_SMEM>>>(w_in);
    dwgelu_kernel<<<dim3(HH/8, HID), 256>>>(w_dw);
    ffn_out_kernel<<<288, 192, FOUT_SMEM>>>(w_out, out);
}